// round 5
// baseline (speedup 1.0000x reference)
#include <cuda_runtime.h>
#include <cstdint>

#define H       128
#define NHEAD   8
#define N_MAX   50000
#define NRELMX  64
#define TEN     32
#define GPAD    36
#define TILE_E  128
#define NT      512

// ---------------- global scratch -------------------------------------------
__device__ float g_Q  [N_MAX * H];
__device__ float g_S1 [N_MAX * H];
__device__ float g_R2x[NRELMX * H];
__device__ float g_denom[N_MAX * NHEAD];

// ---------------- smem layout (edge kernel) --------------------------------
#define OFF_W     0        // w_s[k][c] fp32: 128 x 256 = 131072 B
#define OFF_G     131072   // g_t[k][e] fp32 swizzled: 128 x 128 = 65536 B
#define OFF_PS    131072   // aliases g_t after GEMM: ps[e][16] = 8192 B
#define OFF_BK    196608
#define OFF_BV    197120
#define OFF_B1    197632
#define OFF_W2    198144
#define OFF_DST   198656
#define OFF_SRC   199168
#define OFF_ET    199680
#define OFF_TM    200192
#define OFF_SS    200704
#define OFF_WS    201216   // w_sm[e][8] = 4096 B
#define OFF_HP    205312   // 512 floats
#define SMEM_EDGE 207360

// ---------------- asm helpers ----------------------------------------------
#define F2MA(acc, a, b) asm("fma.rn.f32x2 %0, %1, %2, %0;" : "+l"(acc) : "l"(a), "l"(b))
#define DUP2(d, s)      asm("mov.b64 %0, {%1,%1};" : "=l"(d) : "f"(s))
#define UNPK(lo, hi, p) asm("mov.b64 {%0,%1}, %2;" : "=f"(lo), "=f"(hi) : "l"(p))

// ---------------- init -----------------------------------------------------
__global__ void k_init(float* __restrict__ out, int N, int outElems) {
    int i = blockIdx.x * blockDim.x + threadIdx.x;
    int stride = gridDim.x * blockDim.x;
    for (int idx = i; idx < outElems; idx += stride) out[idx] = 0.f;
    for (int idx = i; idx < N * NHEAD; idx += stride) g_denom[idx] = 0.f;
}

// ---------------- R2x[r] = rel[r] @ W1[128:256] + W1[256] ------------------
__global__ void k_rel(const float* __restrict__ rel, const float* __restrict__ W1) {
    int r = blockIdx.x, j = threadIdx.x;
    float acc = W1[256 * H + j];
    for (int i = 0; i < H; i++)
        acc += rel[r * H + i] * W1[(H + i) * H + j];
    g_R2x[r * H + j] = acc;
}

// ---------------- node precompute: Q = x@Wq+bq, S1 = x@W1[:128] ------------
__global__ void __launch_bounds__(128) k_node(
    const float* __restrict__ x, const float* __restrict__ Wq,
    const float* __restrict__ bq, const float* __restrict__ W1, int N)
{
    __shared__ __align__(16) float xt[H * GPAD];
    int n0 = blockIdx.x * TEN;
    int j = threadIdx.x;
    int cnt = min(TEN, N - n0);
    for (int e = 0; e < TEN; e++)
        xt[j * GPAD + e] = (e < cnt) ? x[(size_t)(n0 + e) * H + j] : 0.f;
    __syncthreads();

    unsigned long long aq[TEN / 2], as_[TEN / 2];
#pragma unroll
    for (int i = 0; i < TEN / 2; i++) { aq[i] = 0ull; as_[i] = 0ull; }
    for (int kk = 0; kk < H; kk++) {
        float wq = Wq[kk * H + j];
        float w1 = W1[kk * H + j];
        unsigned long long wq2, w12;
        DUP2(wq2, wq);
        DUP2(w12, w1);
        const ulonglong2* gp = (const ulonglong2*)(&xt[kk * GPAD]);
#pragma unroll
        for (int q4 = 0; q4 < TEN / 4; q4++) {
            ulonglong2 gg = gp[q4];
            F2MA(aq[q4 * 2],      gg.x, wq2);
            F2MA(aq[q4 * 2 + 1],  gg.y, wq2);
            F2MA(as_[q4 * 2],     gg.x, w12);
            F2MA(as_[q4 * 2 + 1], gg.y, w12);
        }
    }
    float bqj = bq[j];
    for (int e = 0; e < cnt; e++) {
        float vq = (e & 1) ? __uint_as_float((unsigned)(aq[e >> 1] >> 32))
                           : __uint_as_float((unsigned)(aq[e >> 1] & 0xFFFFFFFFull));
        float vs = (e & 1) ? __uint_as_float((unsigned)(as_[e >> 1] >> 32))
                           : __uint_as_float((unsigned)(as_[e >> 1] & 0xFFFFFFFFull));
        g_Q [(n0 + e) * H + j] = vq + bqj;
        g_S1[(n0 + e) * H + j] = vs;
    }
}

// ---------------- persistent fused edge kernel (fp32x2 SGEMM) --------------
__global__ void __launch_bounds__(NT, 1) k_edge(
    const float* __restrict__ x, const float* __restrict__ ts,
    const int* __restrict__ src, const int* __restrict__ dst, const int* __restrict__ et,
    const float* __restrict__ etime, const float* __restrict__ rel,
    const float* __restrict__ Wk, const float* __restrict__ Wv,
    const float* __restrict__ bk, const float* __restrict__ bv,
    const float* __restrict__ b1, const float* __restrict__ W2,
    const float* __restrict__ b2, const float* __restrict__ tcp,
    float* __restrict__ out, int E, int ntiles)
{
    extern __shared__ __align__(16) char smc[];
    int tid = threadIdx.x, wid = tid >> 5, lane = tid & 31;

    float* bk_s  = (float*)(smc + OFF_BK);
    float* bv_s  = (float*)(smc + OFF_BV);
    float* b1_s  = (float*)(smc + OFF_B1);
    float* w2_s  = (float*)(smc + OFF_W2);
    int*   dst_s = (int*)  (smc + OFF_DST);
    int*   src_s = (int*)  (smc + OFF_SRC);
    int*   et_s  = (int*)  (smc + OFF_ET);
    float* tm_s  = (float*)(smc + OFF_TM);
    float* ss_s  = (float*)(smc + OFF_SS);
    float* w_sm  = (float*)(smc + OFF_WS);
    float* hp_s  = (float*)(smc + OFF_HP);
    float* ps    = (float*)(smc + OFF_PS);

    // stage weights w_s[k][c] = (c<128 ? Wk[k][c] : Wv[k][c-128]) fp32
    {
        float4* wd = (float4*)(smc + OFF_W);
        for (int i = tid; i < 8192; i += NT) {
            int k = i >> 6, c4 = i & 63;
            float4 v = (c4 < 32) ? __ldg((const float4*)(Wk + (size_t)k * H) + c4)
                                 : __ldg((const float4*)(Wv + (size_t)k * H) + (c4 - 32));
            wd[i] = v;
        }
    }
    if (tid < H) { bk_s[tid] = bk[tid]; bv_s[tid] = bv[tid]; b1_s[tid] = b1[tid]; w2_s[tid] = W2[tid]; }
    __syncthreads();

    float inv_tc = 1.f / (fabsf(tcp[0]) + 1e-9f);
    float b2v = b2[0];

    // GEMM tile mapping: warp covers 32 edges x 64 cols; thread 8e x 8c
    int ew0 = (wid & 3) * 32, cw0 = (wid >> 2) * 64;
    int erow = ew0 + ((lane >> 3) << 3);
    int bcol = cw0 + ((lane & 7) << 3);
    bool isK = (wid >> 2) < 2;

    // hoisted per-thread biases for epilogue
    float bias_l[8];
#pragma unroll
    for (int j = 0; j < 8; j++)
        bias_l[j] = isK ? bk_s[bcol + j] : bv_s[bcol - 128 + j];

    // gather mapping
    int ge = tid >> 2, gq = tid & 3;
    int ges = (ge + 8 * gq) & 127;

    for (int t = blockIdx.x; t < ntiles; t += gridDim.x) {
        int e0 = t * TILE_E;
        int cnt = min(TILE_E, E - e0);

        // ---- phase 0: edge meta + time gate ----
        if (tid < TILE_E) {
            float tm = 0.f;
            if (tid < cnt) {
                int ee = e0 + tid;
                int d = dst[ee];
                src_s[tid] = src[ee]; dst_s[tid] = d; et_s[tid] = et[ee];
                float dt = (ts[d] - etime[ee]) * inv_tc;
                tm = 1.f / (1.f + expf(-dt));
            } else { src_s[tid] = 0; dst_s[tid] = 0; et_s[tid] = 0; }
            tm_s[tid] = tm;
        }
        __syncthreads();

        // ---- phase 1: gather g = x[src]*rel[et] -> swizzled g_t + gating ----
        {
            int sn = src_s[ge], rr = et_s[ge];
            float tme = tm_s[ge];
            const float4* xp  = (const float4*)(x     + (size_t)sn * H) + gq * 8;
            const float4* rp  = (const float4*)(rel   + (size_t)rr * H) + gq * 8;
            const float4* sp  = (const float4*)(g_S1  + (size_t)sn * H) + gq * 8;
            const float4* r2p = (const float4*)(g_R2x + (size_t)rr * H) + gq * 8;
            char* gcol = smc + OFF_G + ges * 4;
            float hacc = 0.f;
#pragma unroll
            for (int i = 0; i < 8; i++) {
                float4 xv = __ldg(xp + i), rv = __ldg(rp + i);
                float4 s1 = __ldg(sp + i), r2 = __ldg(r2p + i);
                int col = gq * 32 + i * 4;
                float4 b14 = *(const float4*)(b1_s + col);
                float4 w24 = *(const float4*)(w2_s + col);
                float g0 = xv.x * rv.x, g1 = xv.y * rv.y, g2 = xv.z * rv.z, g3 = xv.w * rv.w;
                hacc += fmaxf(fmaf(tme, r2.x, s1.x + b14.x), 0.f) * w24.x;
                hacc += fmaxf(fmaf(tme, r2.y, s1.y + b14.y), 0.f) * w24.y;
                hacc += fmaxf(fmaf(tme, r2.z, s1.z + b14.z), 0.f) * w24.z;
                hacc += fmaxf(fmaf(tme, r2.w, s1.w + b14.w), 0.f) * w24.w;
                *(float*)(gcol + (size_t)(col + 0) * 512) = g0;
                *(float*)(gcol + (size_t)(col + 1) * 512) = g1;
                *(float*)(gcol + (size_t)(col + 2) * 512) = g2;
                *(float*)(gcol + (size_t)(col + 3) * 512) = g3;
            }
            hp_s[tid] = hacc;
        }
        __syncthreads();

        // ---- phase 2: dw = sigmoid(h.W2+b2); s = tm*dw ----
        if (tid < TILE_E) {
            float hsum = hp_s[4 * tid] + hp_s[4 * tid + 1] + hp_s[4 * tid + 2] + hp_s[4 * tid + 3];
            float dw = 1.f / (1.f + expf(-(hsum + b2v)));
            ss_s[tid] = tm_s[tid] * dw;
        }
        __syncthreads();

        // ---- phase 3: GEMM 128x256x128 via fp32x2 FFMA, 8e x 8c / thread ----
        unsigned long long acc[8][4];
#pragma unroll
        for (int e = 0; e < 8; e++)
#pragma unroll
            for (int c = 0; c < 4; c++) acc[e][c] = 0ull;
        {
            const char* gb = smc + OFF_G;
            const char* wb = smc + OFF_W;
#pragma unroll 4
            for (int k = 0; k < H; k++) {
                int es = (erow + ((k >> 5) & 3) * 8) & 127;
                const char* grow = gb + (size_t)k * 512 + es * 4;
                float4 a01 = *(const float4*)(grow);
                float4 a23 = *(const float4*)(grow + 16);
                const char* wrow = wb + (size_t)k * 1024 + bcol * 4;
                ulonglong2 b01 = *(const ulonglong2*)(wrow);
                ulonglong2 b23 = *(const ulonglong2*)(wrow + 16);
                unsigned long long ad[8];
                DUP2(ad[0], a01.x); DUP2(ad[1], a01.y); DUP2(ad[2], a01.z); DUP2(ad[3], a01.w);
                DUP2(ad[4], a23.x); DUP2(ad[5], a23.y); DUP2(ad[6], a23.z); DUP2(ad[7], a23.w);
#pragma unroll
                for (int e = 0; e < 8; e++) {
                    F2MA(acc[e][0], ad[e], b01.x);
                    F2MA(acc[e][1], ad[e], b01.y);
                    F2MA(acc[e][2], ad[e], b23.x);
                    F2MA(acc[e][3], ad[e], b23.y);
                }
            }
        }
        __syncthreads();   // g_t free; ps aliases it

        // ---- phase S: K-warps -> per-(edge, 8col-group) score partials ----
        if (isK) {
#pragma unroll
            for (int ei = 0; ei < 8; ei++) {
                int e = erow + ei;
                int d = dst_s[e];
                float se = ss_s[e];
                const float4* qp = (const float4*)(g_Q + (size_t)d * H + bcol);
                float4 q0 = __ldg(qp), q1 = __ldg(qp + 1);
                float lo, hi, part;
                UNPK(lo, hi, acc[ei][0]);
                part  = q0.x * fmaf(lo, se, bias_l[0]) + q0.y * fmaf(hi, se, bias_l[1]);
                UNPK(lo, hi, acc[ei][1]);
                part += q0.z * fmaf(lo, se, bias_l[2]) + q0.w * fmaf(hi, se, bias_l[3]);
                UNPK(lo, hi, acc[ei][2]);
                part += q1.x * fmaf(lo, se, bias_l[4]) + q1.y * fmaf(hi, se, bias_l[5]);
                UNPK(lo, hi, acc[ei][3]);
                part += q1.z * fmaf(lo, se, bias_l[6]) + q1.w * fmaf(hi, se, bias_l[7]);
                ps[e * 16 + (bcol >> 3)] = part;
            }
        }
        __syncthreads();

        // ---- phase W: attn weights + denom scatter ----
        if (tid < 256) {
            int e = tid >> 1, hb = (tid & 1) * 4;
            float w0 = expf((ps[e * 16 + 2 * (hb + 0)] + ps[e * 16 + 2 * (hb + 0) + 1]) * 0.25f);
            float w1 = expf((ps[e * 16 + 2 * (hb + 1)] + ps[e * 16 + 2 * (hb + 1) + 1]) * 0.25f);
            float w2 = expf((ps[e * 16 + 2 * (hb + 2)] + ps[e * 16 + 2 * (hb + 2) + 1]) * 0.25f);
            float w3 = expf((ps[e * 16 + 2 * (hb + 3)] + ps[e * 16 + 2 * (hb + 3) + 1]) * 0.25f);
            w_sm[e * 8 + hb + 0] = w0;
            w_sm[e * 8 + hb + 1] = w1;
            w_sm[e * 8 + hb + 2] = w2;
            w_sm[e * 8 + hb + 3] = w3;
            if (e < cnt) {
                float* dp = &g_denom[(size_t)dst_s[e] * NHEAD + hb];
                asm volatile("red.global.add.v4.f32 [%0], {%1,%2,%3,%4};"
                             :: "l"(dp), "f"(w0), "f"(w1), "f"(w2), "f"(w3) : "memory");
            }
        }
        __syncthreads();

        // ---- phase V: V-warps -> weighted V scatter ----
        if (!isK) {
            int vcol = bcol - 128;
            int hv = vcol >> 4;   // all 8 cols in one head
#pragma unroll
            for (int ei = 0; ei < 8; ei++) {
                int e = erow + ei;
                if (e >= cnt) continue;
                int d = dst_s[e];
                float se = ss_s[e];
                float ww = w_sm[e * 8 + hv];
                float* orow = out + (size_t)d * H + vcol;
                float lo, hi;
                UNPK(lo, hi, acc[ei][0]);
                float v0 = fmaf(lo, se, bias_l[0]) * ww, v1 = fmaf(hi, se, bias_l[1]) * ww;
                UNPK(lo, hi, acc[ei][1]);
                float v2 = fmaf(lo, se, bias_l[2]) * ww, v3 = fmaf(hi, se, bias_l[3]) * ww;
                asm volatile("red.global.add.v4.f32 [%0], {%1,%2,%3,%4};"
                             :: "l"(orow), "f"(v0), "f"(v1), "f"(v2), "f"(v3) : "memory");
                UNPK(lo, hi, acc[ei][2]);
                float v4 = fmaf(lo, se, bias_l[4]) * ww, v5 = fmaf(hi, se, bias_l[5]) * ww;
                UNPK(lo, hi, acc[ei][3]);
                float v6 = fmaf(lo, se, bias_l[6]) * ww, v7 = fmaf(hi, se, bias_l[7]) * ww;
                asm volatile("red.global.add.v4.f32 [%0], {%1,%2,%3,%4};"
                             :: "l"(orow + 4), "f"(v4), "f"(v5), "f"(v6), "f"(v7) : "memory");
            }
        }
        __syncthreads();
    }
}

// ---------------- normalize ------------------------------------------------
__global__ void k_norm(float* __restrict__ out, int N)
{
    int idx = blockIdx.x * blockDim.x + threadIdx.x;
    if (idx >= N * H) return;
    int n = idx >> 7, jj = idx & (H - 1);
    float dnm = g_denom[n * NHEAD + (jj >> 4)];
    float v = out[idx];
    out[idx] = (dnm > 0.f) ? v / dnm : 0.f;
}

// ---------------- launch ---------------------------------------------------
extern "C" void kernel_launch(void* const* d_in, const int* in_sizes, int n_in,
                              void* d_out, int out_size)
{
    const float* x     = (const float*)d_in[0];
    const float* ts    = (const float*)d_in[1];
    const int*   src   = (const int*)  d_in[2];
    const int*   dst   = (const int*)  d_in[3];
    const int*   etyp  = (const int*)  d_in[4];
    const float* etime = (const float*)d_in[5];
    const float* rel   = (const float*)d_in[6];
    const float* Wq    = (const float*)d_in[7];
    const float* bq    = (const float*)d_in[8];
    const float* Wk    = (const float*)d_in[9];
    const float* bk    = (const float*)d_in[10];
    const float* Wv    = (const float*)d_in[11];
    const float* bv    = (const float*)d_in[12];
    const float* W1    = (const float*)d_in[13];
    const float* b1    = (const float*)d_in[14];
    const float* W2    = (const float*)d_in[15];
    const float* b2    = (const float*)d_in[16];
    const float* tcp   = (const float*)d_in[17];

    int N    = in_sizes[0] / H;
    int E    = in_sizes[2];
    int NREL = in_sizes[6] / H;
    float* out = (float*)d_out;
    int ntiles = (E + TILE_E - 1) / TILE_E;

    static int smem_set = 0;
    if (!smem_set) {
        cudaFuncSetAttribute(k_edge, cudaFuncAttributeMaxDynamicSharedMemorySize, SMEM_EDGE);
        smem_set = 1;
    }

    k_init<<<2048, 256>>>(out, N, out_size);
    k_rel <<<NREL, H>>>(rel, W1);
    k_node<<<(N + TEN - 1) / TEN, H>>>(x, Wq, bq, W1, N);
    k_edge<<<148, NT, SMEM_EDGE>>>(x, ts, src, dst, etyp, etime, rel,
                                   Wk, Wv, bk, bv, b1, W2, b2, tcp, out, E, ntiles);
    k_norm<<<(N * H + 255) / 256, 256>>>(out, N);
}

// round 6
// speedup vs baseline: 1.2697x; 1.2697x over previous
#include <cuda_runtime.h>
#include <cuda_bf16.h>
#include <cstdint>

#define H       128
#define NHEAD   8
#define N_MAX   50000
#define NRELMX  64
#define TEN     32
#define GPAD    36
#define TILE_E  128
#define NT      512

// ---------------- global scratch -------------------------------------------
__device__ float g_Q  [N_MAX * H];
__device__ float g_S1 [N_MAX * H];
__device__ float g_R2x[NRELMX * H];
__device__ float g_denom[N_MAX * NHEAD];
__device__ __nv_bfloat16 g_Bhi[256 * H];   // [n][k], 256B rows, XOR-16B swizzle
__device__ __nv_bfloat16 g_Blo[256 * H];

// ---------------- smem layout ----------------------------------------------
#define OFF_BHI   0
#define OFF_BLO   65536
#define OFF_AHI   131072
#define OFF_ALO   163840
#define OFF_KV    131072   // aliases A region (used after GEMM)
#define OFF_BK    196608
#define OFF_BV    197120
#define OFF_B1    197632
#define OFF_W2    198144
#define OFF_DST   198656
#define OFF_SRC   199168
#define OFF_ET    199680
#define OFF_TM    200192
#define OFF_SS    200704
#define OFF_WS    201216   // w_sm[e][8] = 4096 B
#define SMEM_EDGE 207360

// ---------------- helpers --------------------------------------------------
__device__ __forceinline__ uint32_t s2u(const void* p) {
    uint32_t a;
    asm("{ .reg .u64 t; cvta.to.shared.u64 t, %1; cvt.u32.u64 %0, t; }" : "=r"(a) : "l"(p));
    return a;
}
__device__ __forceinline__ void ldsm4(uint32_t* r, uint32_t addr) {
    asm volatile("ldmatrix.sync.aligned.m8n8.x4.shared.b16 {%0,%1,%2,%3}, [%4];"
                 : "=r"(r[0]), "=r"(r[1]), "=r"(r[2]), "=r"(r[3]) : "r"(addr));
}
__device__ __forceinline__ void mma16816(float* c, const uint32_t* a, const uint32_t* b) {
    asm volatile(
        "mma.sync.aligned.m16n8k16.row.col.f32.bf16.bf16.f32 "
        "{%0,%1,%2,%3}, {%4,%5,%6,%7}, {%8,%9}, {%0,%1,%2,%3};"
        : "+f"(c[0]), "+f"(c[1]), "+f"(c[2]), "+f"(c[3])
        : "r"(a[0]), "r"(a[1]), "r"(a[2]), "r"(a[3]), "r"(b[0]), "r"(b[1]));
}
#define DUP2(d, s) asm("mov.b64 %0, {%1,%1};" : "=l"(d) : "f"(s))
#define F2MA(acc, a, b) asm("fma.rn.f32x2 %0, %1, %2, %0;" : "+l"(acc) : "l"(a), "l"(b))

// ---------------- init -----------------------------------------------------
__global__ void k_init(float* __restrict__ out, int N, int outElems) {
    int i = blockIdx.x * blockDim.x + threadIdx.x;
    int stride = gridDim.x * blockDim.x;
    for (int idx = i; idx < outElems; idx += stride) out[idx] = 0.f;
    for (int idx = i; idx < N * NHEAD; idx += stride) g_denom[idx] = 0.f;
}

// ---------------- R2x[r] = rel[r] @ W1[128:256] + W1[256] ------------------
__global__ void k_rel(const float* __restrict__ rel, const float* __restrict__ W1) {
    int r = blockIdx.x, j = threadIdx.x;
    float acc = W1[256 * H + j];
    for (int i = 0; i < H; i++)
        acc += rel[r * H + i] * W1[(H + i) * H + j];
    g_R2x[r * H + j] = acc;
}

// ---------------- weight images: BT[n][k] = W[k][n], bf16 hi/lo ------------
__global__ void k_prepw(const float* __restrict__ Wk, const float* __restrict__ Wv) {
    int n = blockIdx.x, k = threadIdx.x;
    float w = (n < H) ? Wk[k * H + n] : Wv[k * H + (n - H)];
    __nv_bfloat16 hi = __float2bfloat16(w);
    float lo = w - __bfloat162float(hi);
    unsigned kb = (unsigned)k * 2u;
    unsigned phys = (unsigned)n * 256u + (kb ^ ((unsigned)(n & 7) << 4));
    *(__nv_bfloat16*)((char*)g_Bhi + phys) = hi;
    *(__nv_bfloat16*)((char*)g_Blo + phys) = __float2bfloat16(lo);
}

// ---------------- node precompute: Q = x@Wq+bq, S1 = x@W1[:128] ------------
__global__ void __launch_bounds__(128) k_node(
    const float* __restrict__ x, const float* __restrict__ Wq,
    const float* __restrict__ bq, const float* __restrict__ W1, int N)
{
    __shared__ __align__(16) float xt[H * GPAD];
    int n0 = blockIdx.x * TEN;
    int j = threadIdx.x;
    int cnt = min(TEN, N - n0);
    for (int e = 0; e < TEN; e++)
        xt[j * GPAD + e] = (e < cnt) ? x[(size_t)(n0 + e) * H + j] : 0.f;
    __syncthreads();

    unsigned long long aq[TEN / 2], as_[TEN / 2];
#pragma unroll
    for (int i = 0; i < TEN / 2; i++) { aq[i] = 0ull; as_[i] = 0ull; }
    for (int kk = 0; kk < H; kk++) {
        float wq = Wq[kk * H + j];
        float w1 = W1[kk * H + j];
        unsigned long long wq2, w12;
        DUP2(wq2, wq);
        DUP2(w12, w1);
        const ulonglong2* gp = (const ulonglong2*)(&xt[kk * GPAD]);
#pragma unroll
        for (int q4 = 0; q4 < TEN / 4; q4++) {
            ulonglong2 gg = gp[q4];
            F2MA(aq[q4 * 2],      gg.x, wq2);
            F2MA(aq[q4 * 2 + 1],  gg.y, wq2);
            F2MA(as_[q4 * 2],     gg.x, w12);
            F2MA(as_[q4 * 2 + 1], gg.y, w12);
        }
    }
    float bqj = bq[j];
    for (int e = 0; e < cnt; e++) {
        float vq = (e & 1) ? __uint_as_float((unsigned)(aq[e >> 1] >> 32))
                           : __uint_as_float((unsigned)(aq[e >> 1] & 0xFFFFFFFFull));
        float vs = (e & 1) ? __uint_as_float((unsigned)(as_[e >> 1] >> 32))
                           : __uint_as_float((unsigned)(as_[e >> 1] & 0xFFFFFFFFull));
        g_Q [(n0 + e) * H + j] = vq + bqj;
        g_S1[(n0 + e) * H + j] = vs;
    }
}

// ---------------- persistent fused edge kernel (mma.sync bf16, m64n32) -----
__global__ void __launch_bounds__(NT, 1) k_edge_mma(
    const float* __restrict__ x, const float* __restrict__ ts,
    const int* __restrict__ src, const int* __restrict__ dst, const int* __restrict__ et,
    const float* __restrict__ etime, const float* __restrict__ rel,
    const float* __restrict__ bk, const float* __restrict__ bv,
    const float* __restrict__ b1, const float* __restrict__ W2,
    const float* __restrict__ b2, const float* __restrict__ tcp,
    float* __restrict__ out, int E, int ntiles)
{
    extern __shared__ __align__(1024) char smc[];
    uint32_t smb = s2u(smc);
    int tid = threadIdx.x, wid = tid >> 5, lane = tid & 31;

    float* bk_s  = (float*)(smc + OFF_BK);
    float* bv_s  = (float*)(smc + OFF_BV);
    float* b1_s  = (float*)(smc + OFF_B1);
    float* w2_s  = (float*)(smc + OFF_W2);
    int*   dst_s = (int*)  (smc + OFF_DST);
    int*   src_s = (int*)  (smc + OFF_SRC);
    int*   et_s  = (int*)  (smc + OFF_ET);
    float* tm_s  = (float*)(smc + OFF_TM);
    float* ss_s  = (float*)(smc + OFF_SS);
    float* w_sm  = (float*)(smc + OFF_WS);

    // stage B images (hi/lo) into smem once per CTA
    {
        float4* d0 = (float4*)(smc + OFF_BHI);
        float4* d1 = (float4*)(smc + OFF_BLO);
        const float4* s0 = (const float4*)g_Bhi;
        const float4* s1 = (const float4*)g_Blo;
        for (int i = tid; i < 4096; i += NT) d0[i] = s0[i];
        for (int i = tid; i < 4096; i += NT) d1[i] = s1[i];
    }
    if (tid < H) { bk_s[tid] = bk[tid]; bv_s[tid] = bv[tid]; b1_s[tid] = b1[tid]; w2_s[tid] = W2[tid]; }
    __syncthreads();

    float inv_tc = 1.f / (fabsf(tcp[0]) + 1e-9f);
    float b2v = b2[0];

    // ---- per-warp GEMM tiling: m64 x n32, 2x8 warp grid ----
    int warp_row = wid & 1;        // edge half: rows 0-63 / 64-127
    int warp_col = wid >> 1;       // 0..7, 32 cols each
    int n0 = warp_col * 32;
    bool isK = (n0 < 128);

    // ldmatrix A lane addressing (m16k16 hi frag per mt)
    int ra = lane & 7, ha = (lane >> 3) & 1, kh = lane >> 4;
    uint32_t aXor = (uint32_t)ra << 4;
    uint32_t aKh = (uint32_t)(kh * 16);
    uint32_t aRowBase = smb + OFF_AHI + (uint32_t)(warp_row * 64 + ha * 8 + ra) * 256u;

    // ldmatrix B lane addressing (n16k16 per ldsm4)
    int qb = lane >> 3, rb = lane & 7;
    uint32_t bXor = (uint32_t)rb << 4;
    uint32_t bKh = (uint32_t)((qb & 1) * 16);
    uint32_t bRow0 = smb + OFF_BHI + (uint32_t)(n0 + (qb >> 1) * 8 + rb) * 256u;
    uint32_t bRow1 = bRow0 + 16u * 256u;

    int r4 = lane >> 2, c2 = (lane & 3) * 2;

    // gather mapping
    int ge = tid >> 2, gq = tid & 3;

    for (int t = blockIdx.x; t < ntiles; t += gridDim.x) {
        int e0 = t * TILE_E;
        int cnt = min(TILE_E, E - e0);

        // ---- phase 0: edge meta + time gate ----
        if (tid < TILE_E) {
            float tm = 0.f;
            if (tid < cnt) {
                int ee = e0 + tid;
                int d = dst[ee];
                src_s[tid] = src[ee]; dst_s[tid] = d; et_s[tid] = et[ee];
                float dt = (ts[d] - etime[ee]) * inv_tc;
                tm = 1.f / (1.f + expf(-dt));
            } else { src_s[tid] = 0; dst_s[tid] = 0; et_s[tid] = 0; }
            tm_s[tid] = tm;
        }
        __syncthreads();

        // ---- phase 1: gather g = x[src]*rel[et] -> bf16 hi/lo A + dw ----
        {
            int sn = src_s[ge], rr = et_s[ge];
            float tme = tm_s[ge];
            const float4* xp  = (const float4*)(x     + (size_t)sn * H) + gq * 8;
            const float4* rp  = (const float4*)(rel   + (size_t)rr * H) + gq * 8;
            const float4* sp  = (const float4*)(g_S1  + (size_t)sn * H) + gq * 8;
            const float4* r2p = (const float4*)(g_R2x + (size_t)rr * H) + gq * 8;
            char* Ahi = smc + OFF_AHI + ge * 256;
            char* Alo = smc + OFF_ALO + ge * 256;
            unsigned xr = (unsigned)(ge & 7) << 4;
            float hacc = 0.f;
#pragma unroll
            for (int i = 0; i < 8; i++) {
                float4 xv = __ldg(xp + i), rv = __ldg(rp + i);
                float4 s1 = __ldg(sp + i), r2 = __ldg(r2p + i);
                int col = gq * 32 + i * 4;
                float4 b14 = *(const float4*)(b1_s + col);
                float4 w24 = *(const float4*)(w2_s + col);
                float g0 = xv.x * rv.x, g1 = xv.y * rv.y, g2 = xv.z * rv.z, g3 = xv.w * rv.w;
                hacc += fmaxf(fmaf(tme, r2.x, s1.x + b14.x), 0.f) * w24.x;
                hacc += fmaxf(fmaf(tme, r2.y, s1.y + b14.y), 0.f) * w24.y;
                hacc += fmaxf(fmaf(tme, r2.z, s1.z + b14.z), 0.f) * w24.z;
                hacc += fmaxf(fmaf(tme, r2.w, s1.w + b14.w), 0.f) * w24.w;
                __nv_bfloat162 h01 = __floats2bfloat162_rn(g0, g1);
                __nv_bfloat162 h23 = __floats2bfloat162_rn(g2, g3);
                float l0 = g0 - __bfloat162float(h01.x);
                float l1 = g1 - __bfloat162float(h01.y);
                float l2 = g2 - __bfloat162float(h23.x);
                float l3 = g3 - __bfloat162float(h23.y);
                __nv_bfloat162 l01 = __floats2bfloat162_rn(l0, l1);
                __nv_bfloat162 l23 = __floats2bfloat162_rn(l2, l3);
                unsigned kb = (unsigned)(gq * 64 + i * 8);
                uint2 uh; uh.x = *(unsigned*)&h01; uh.y = *(unsigned*)&h23;
                uint2 ul; ul.x = *(unsigned*)&l01; ul.y = *(unsigned*)&l23;
                *(uint2*)(Ahi + (kb ^ xr)) = uh;
                *(uint2*)(Alo + (kb ^ xr)) = ul;
            }
            // dw = sigmoid(h.W2+b2) reduced across the 4 lanes of this edge
            hacc += __shfl_xor_sync(0xFFFFFFFFu, hacc, 1);
            hacc += __shfl_xor_sync(0xFFFFFFFFu, hacc, 2);
            if ((tid & 3) == 0) {
                float dw = 1.f / (1.f + expf(-(hacc + b2v)));
                ss_s[ge] = tm_s[ge] * dw;
            }
        }
        __syncthreads();

        // ---- phase 2: GEMM 128x256x128, 3-pass 3xBF16, m64n32 per warp ----
        float acc[4][4][4];
#pragma unroll
        for (int mt = 0; mt < 4; mt++)
#pragma unroll
            for (int ng = 0; ng < 4; ng++)
#pragma unroll
                for (int i = 0; i < 4; i++) acc[mt][ng][i] = 0.f;

        for (int ks = 0; ks < 8; ks++) {
            uint32_t kbB = ((uint32_t)(ks * 32) + bKh) ^ bXor;
            uint32_t bh[8], bl[8];
            ldsm4(bh + 0, bRow0 + kbB);
            ldsm4(bh + 4, bRow1 + kbB);
            ldsm4(bl + 0, bRow0 + kbB + (OFF_BLO - OFF_BHI));
            ldsm4(bl + 4, bRow1 + kbB + (OFF_BLO - OFF_BHI));
            uint32_t kbA = ((uint32_t)(ks * 32) + aKh) ^ aXor;
#pragma unroll
            for (int mt = 0; mt < 4; mt++) {
                uint32_t aoff = aRowBase + (uint32_t)(mt * 16) * 256u + kbA;
                uint32_t ah[4], al[4];
                ldsm4(ah, aoff);
                ldsm4(al, aoff + (OFF_ALO - OFF_AHI));
#pragma unroll
                for (int ng = 0; ng < 4; ng++) {
                    mma16816(acc[mt][ng], ah, bh + ng * 2);
                    mma16816(acc[mt][ng], al, bh + ng * 2);
                    mma16816(acc[mt][ng], ah, bl + ng * 2);
                }
            }
        }
        __syncthreads();   // A tile no longer needed; KV buf aliases it

        // ---- stage K accums to smem (swizzled rows of 512B) ----
        if (isK) {
#pragma unroll
            for (int mt = 0; mt < 4; mt++) {
#pragma unroll
                for (int ng = 0; ng < 4; ng++) {
                    int ee = warp_row * 64 + mt * 16 + r4;
                    unsigned jb = (unsigned)((n0 + ng * 8 + c2) * 4);
                    char* base = smc + OFF_KV;
                    *(float2*)(base + ee * 512 + (jb ^ ((unsigned)(ee & 31) << 4))) =
                        make_float2(acc[mt][ng][0], acc[mt][ng][1]);
                    int ee2 = ee + 8;
                    *(float2*)(base + ee2 * 512 + (jb ^ ((unsigned)(ee2 & 31) << 4))) =
                        make_float2(acc[mt][ng][2], acc[mt][ng][3]);
                }
            }
        }
        __syncthreads();

        // ---- score phase: thread covers 32 cols (2 heads) of one edge ----
        {
            int qq = wid & 3;
            int e = (wid >> 2) * 32 + lane;
            int d2 = dst_s[e];
            float sce = ss_s[e];
            bool valid = (e < cnt);
            const float* qrow = g_Q + (size_t)d2 * H;
            char* kbase = smc + OFF_KV + e * 512;
            unsigned xr = (unsigned)(e & 31) << 4;
            float s0 = 0.f, s1 = 0.f;
#pragma unroll
            for (int i = 0; i < 8; i++) {
                unsigned jb = (unsigned)(qq * 128 + i * 16);
                float4 kr = *(float4*)(kbase + (jb ^ xr));
                int j = qq * 32 + i * 4;
                float4 q4 = __ldg((const float4*)(qrow + j));
                float k0 = fmaf(kr.x, sce, bk_s[j + 0]);
                float k1 = fmaf(kr.y, sce, bk_s[j + 1]);
                float k2 = fmaf(kr.z, sce, bk_s[j + 2]);
                float k3 = fmaf(kr.w, sce, bk_s[j + 3]);
                float dp = q4.x * k0 + q4.y * k1 + q4.z * k2 + q4.w * k3;
                if (i < 4) s0 += dp; else s1 += dp;
            }
            float w0 = expf(s0 * 0.25f);
            float w1 = expf(s1 * 0.25f);
            w_sm[e * 8 + 2 * qq + 0] = w0;
            w_sm[e * 8 + 2 * qq + 1] = w1;
            if (valid) {
                float* dp = &g_denom[(size_t)d2 * NHEAD + 2 * qq];
                asm volatile("red.global.add.v2.f32 [%0], {%1,%2};"
                             :: "l"(dp), "f"(w0), "f"(w1) : "memory");
            }
        }
        __syncthreads();

        // ---- stage V accums to smem (same buffer) ----
        if (!isK) {
#pragma unroll
            for (int mt = 0; mt < 4; mt++) {
#pragma unroll
                for (int ng = 0; ng < 4; ng++) {
                    int ee = warp_row * 64 + mt * 16 + r4;
                    unsigned jb = (unsigned)((n0 - 128 + ng * 8 + c2) * 4);
                    char* base = smc + OFF_KV;
                    *(float2*)(base + ee * 512 + (jb ^ ((unsigned)(ee & 31) << 4))) =
                        make_float2(acc[mt][ng][0], acc[mt][ng][1]);
                    int ee2 = ee + 8;
                    *(float2*)(base + ee2 * 512 + (jb ^ ((unsigned)(ee2 & 31) << 4))) =
                        make_float2(acc[mt][ng][2], acc[mt][ng][3]);
                }
            }
        }
        __syncthreads();

        // ---- V scatter phase ----
        {
            int qq = wid & 3;
            int e = (wid >> 2) * 32 + lane;
            int d2 = dst_s[e];
            float sce = ss_s[e];
            bool valid = (e < cnt);
            char* vbase = smc + OFF_KV + e * 512;
            unsigned xr = (unsigned)(e & 31) << 4;
            float* orow = out + (size_t)d2 * H;
#pragma unroll
            for (int i = 0; i < 8; i++) {
                unsigned jb = (unsigned)(qq * 128 + i * 16);
                float4 vr = *(float4*)(vbase + (jb ^ xr));
                int j = qq * 32 + i * 4;
                float ww = w_sm[e * 8 + 2 * qq + (i >> 2)];
                float v0 = fmaf(vr.x, sce, bv_s[j + 0]) * ww;
                float v1 = fmaf(vr.y, sce, bv_s[j + 1]) * ww;
                float v2 = fmaf(vr.z, sce, bv_s[j + 2]) * ww;
                float v3 = fmaf(vr.w, sce, bv_s[j + 3]) * ww;
                if (valid)
                    asm volatile("red.global.add.v4.f32 [%0], {%1,%2,%3,%4};"
                                 :: "l"(orow + j), "f"(v0), "f"(v1), "f"(v2), "f"(v3) : "memory");
            }
        }
        __syncthreads();
    }
}

// ---------------- normalize ------------------------------------------------
__global__ void k_norm(float* __restrict__ out, int N)
{
    int idx = blockIdx.x * blockDim.x + threadIdx.x;
    if (idx >= N * H) return;
    int n = idx >> 7, jj = idx & (H - 1);
    float dnm = g_denom[n * NHEAD + (jj >> 4)];
    float v = out[idx];
    out[idx] = (dnm > 0.f) ? v / dnm : 0.f;
}

// ---------------- launch ---------------------------------------------------
extern "C" void kernel_launch(void* const* d_in, const int* in_sizes, int n_in,
                              void* d_out, int out_size)
{
    const float* x     = (const float*)d_in[0];
    const float* ts    = (const float*)d_in[1];
    const int*   src   = (const int*)  d_in[2];
    const int*   dst   = (const int*)  d_in[3];
    const int*   etyp  = (const int*)  d_in[4];
    const float* etime = (const float*)d_in[5];
    const float* rel   = (const float*)d_in[6];
    const float* Wq    = (const float*)d_in[7];
    const float* bq    = (const float*)d_in[8];
    const float* Wk    = (const float*)d_in[9];
    const float* bk    = (const float*)d_in[10];
    const float* Wv    = (const float*)d_in[11];
    const float* bv    = (const float*)d_in[12];
    const float* W1    = (const float*)d_in[13];
    const float* b1    = (const float*)d_in[14];
    const float* W2    = (const float*)d_in[15];
    const float* b2    = (const float*)d_in[16];
    const float* tcp   = (const float*)d_in[17];

    int N    = in_sizes[0] / H;
    int E    = in_sizes[2];
    int NREL = in_sizes[6] / H;
    float* out = (float*)d_out;
    int ntiles = (E + TILE_E - 1) / TILE_E;

    static int smem_set = 0;
    if (!smem_set) {
        cudaFuncSetAttribute(k_edge_mma, cudaFuncAttributeMaxDynamicSharedMemorySize, SMEM_EDGE);
        smem_set = 1;
    }

    k_init <<<2048, 256>>>(out, N, out_size);
    k_rel  <<<NREL, H>>>(rel, W1);
    k_prepw<<<256, H>>>(Wk, Wv);
    k_node <<<(N + TEN - 1) / TEN, H>>>(x, Wq, bq, W1, N);
    k_edge_mma<<<148, NT, SMEM_EDGE>>>(x, ts, src, dst, etyp, etime, rel,
                                       bk, bv, b1, W2, b2, tcp, out, E, ntiles);
    k_norm <<<(N * H + 255) / 256, 256>>>(out, N);
}

// round 7
// speedup vs baseline: 1.9380x; 1.5263x over previous
#include <cuda_runtime.h>
#include <cuda_fp16.h>
#include <cstdint>

#define H       128
#define NHEAD   8
#define N_MAX   50000
#define NRELMX  64
#define TEN     32
#define GPAD    36
#define TILE_E  128
#define NT      512

// ---------------- global scratch -------------------------------------------
__device__ float g_Q  [N_MAX * H];
__device__ float g_S1 [N_MAX * H];
__device__ float g_R2x[NRELMX * H];
__device__ float g_denom[N_MAX * NHEAD];
__device__ __half g_B[256 * H];   // [n][k] fp16, 256B rows, XOR-16B swizzle

// ---------------- smem layout ----------------------------------------------
#define OFF_B     0        // 65536
#define OFF_A     65536    // 32768 (fp16 A tile)
#define OFF_KV    65536    // aliases A (+32K beyond), 65536 B
#define OFF_BK    131072
#define OFF_BV    131584
#define OFF_B1    132096
#define OFF_W2    132608
#define OFF_DST   133120
#define OFF_SRC   133632
#define OFF_ET    134144
#define OFF_TM    134656
#define OFF_SS    135168
#define OFF_WS    135680   // w_sm[e][8] = 4096
#define SMEM_EDGE 139776

// ---------------- helpers --------------------------------------------------
__device__ __forceinline__ uint32_t s2u(const void* p) {
    uint32_t a;
    asm("{ .reg .u64 t; cvta.to.shared.u64 t, %1; cvt.u32.u64 %0, t; }" : "=r"(a) : "l"(p));
    return a;
}
__device__ __forceinline__ void ldsm4(uint32_t* r, uint32_t addr) {
    asm volatile("ldmatrix.sync.aligned.m8n8.x4.shared.b16 {%0,%1,%2,%3}, [%4];"
                 : "=r"(r[0]), "=r"(r[1]), "=r"(r[2]), "=r"(r[3]) : "r"(addr));
}
__device__ __forceinline__ void mma16816(float* c, const uint32_t* a, const uint32_t* b) {
    asm volatile(
        "mma.sync.aligned.m16n8k16.row.col.f32.f16.f16.f32 "
        "{%0,%1,%2,%3}, {%4,%5,%6,%7}, {%8,%9}, {%0,%1,%2,%3};"
        : "+f"(c[0]), "+f"(c[1]), "+f"(c[2]), "+f"(c[3])
        : "r"(a[0]), "r"(a[1]), "r"(a[2]), "r"(a[3]), "r"(b[0]), "r"(b[1]));
}
#define DUP2(d, s) asm("mov.b64 %0, {%1,%1};" : "=l"(d) : "f"(s))
#define F2MA(acc, a, b) asm("fma.rn.f32x2 %0, %1, %2, %0;" : "+l"(acc) : "l"(a), "l"(b))

// ---------------- init -----------------------------------------------------
__global__ void k_init(float* __restrict__ out, int N, int outElems) {
    int i = blockIdx.x * blockDim.x + threadIdx.x;
    int stride = gridDim.x * blockDim.x;
    for (int idx = i; idx < outElems; idx += stride) out[idx] = 0.f;
    for (int idx = i; idx < N * NHEAD; idx += stride) g_denom[idx] = 0.f;
}

// ---------------- R2x[r] = rel[r] @ W1[128:256] + W1[256] ------------------
__global__ void k_rel(const float* __restrict__ rel, const float* __restrict__ W1) {
    int r = blockIdx.x, j = threadIdx.x;
    float acc = W1[256 * H + j];
    for (int i = 0; i < H; i++)
        acc += rel[r * H + i] * W1[(H + i) * H + j];
    g_R2x[r * H + j] = acc;
}

// ---------------- weight image: BT[n][k] = W[k][n], fp16 -------------------
__global__ void k_prepw(const float* __restrict__ Wk, const float* __restrict__ Wv) {
    int n = blockIdx.x, k = threadIdx.x;
    float w = (n < H) ? Wk[k * H + n] : Wv[k * H + (n - H)];
    unsigned kb = (unsigned)k * 2u;
    unsigned phys = (unsigned)n * 256u + (kb ^ ((unsigned)(n & 7) << 4));
    *(__half*)((char*)g_B + phys) = __float2half_rn(w);
}

// ---------------- node precompute: Q = x@Wq+bq, S1 = x@W1[:128] ------------
__global__ void __launch_bounds__(128) k_node(
    const float* __restrict__ x, const float* __restrict__ Wq,
    const float* __restrict__ bq, const float* __restrict__ W1, int N)
{
    __shared__ __align__(16) float xt[H * GPAD];
    int n0 = blockIdx.x * TEN;
    int j = threadIdx.x;
    int cnt = min(TEN, N - n0);
    for (int e = 0; e < TEN; e++)
        xt[j * GPAD + e] = (e < cnt) ? x[(size_t)(n0 + e) * H + j] : 0.f;
    __syncthreads();

    unsigned long long aq[TEN / 2], as_[TEN / 2];
#pragma unroll
    for (int i = 0; i < TEN / 2; i++) { aq[i] = 0ull; as_[i] = 0ull; }
    for (int kk = 0; kk < H; kk++) {
        float wq = Wq[kk * H + j];
        float w1 = W1[kk * H + j];
        unsigned long long wq2, w12;
        DUP2(wq2, wq);
        DUP2(w12, w1);
        const ulonglong2* gp = (const ulonglong2*)(&xt[kk * GPAD]);
#pragma unroll
        for (int q4 = 0; q4 < TEN / 4; q4++) {
            ulonglong2 gg = gp[q4];
            F2MA(aq[q4 * 2],      gg.x, wq2);
            F2MA(aq[q4 * 2 + 1],  gg.y, wq2);
            F2MA(as_[q4 * 2],     gg.x, w12);
            F2MA(as_[q4 * 2 + 1], gg.y, w12);
        }
    }
    float bqj = bq[j];
    for (int e = 0; e < cnt; e++) {
        float vq = (e & 1) ? __uint_as_float((unsigned)(aq[e >> 1] >> 32))
                           : __uint_as_float((unsigned)(aq[e >> 1] & 0xFFFFFFFFull));
        float vs = (e & 1) ? __uint_as_float((unsigned)(as_[e >> 1] >> 32))
                           : __uint_as_float((unsigned)(as_[e >> 1] & 0xFFFFFFFFull));
        g_Q [(n0 + e) * H + j] = vq + bqj;
        g_S1[(n0 + e) * H + j] = vs;
    }
}

// ---------------- persistent fused edge kernel (fp16 mma.sync, m64n32) -----
__global__ void __launch_bounds__(NT, 1) k_edge_mma(
    const float* __restrict__ x, const float* __restrict__ ts,
    const int* __restrict__ src, const int* __restrict__ dst, const int* __restrict__ et,
    const float* __restrict__ etime, const float* __restrict__ rel,
    const float* __restrict__ bk, const float* __restrict__ bv,
    const float* __restrict__ b1, const float* __restrict__ W2,
    const float* __restrict__ b2, const float* __restrict__ tcp,
    float* __restrict__ out, int E, int ntiles)
{
    extern __shared__ __align__(1024) char smc[];
    uint32_t smb = s2u(smc);
    int tid = threadIdx.x, wid = tid >> 5, lane = tid & 31;

    float* bk_s  = (float*)(smc + OFF_BK);
    float* bv_s  = (float*)(smc + OFF_BV);
    float* b1_s  = (float*)(smc + OFF_B1);
    float* w2_s  = (float*)(smc + OFF_W2);
    int*   dst_s = (int*)  (smc + OFF_DST);
    int*   src_s = (int*)  (smc + OFF_SRC);
    int*   et_s  = (int*)  (smc + OFF_ET);
    float* tm_s  = (float*)(smc + OFF_TM);
    float* ss_s  = (float*)(smc + OFF_SS);
    float* w_sm  = (float*)(smc + OFF_WS);

    // stage B image into smem once per CTA
    {
        float4* d0 = (float4*)(smc + OFF_B);
        const float4* s0 = (const float4*)g_B;
        for (int i = tid; i < 4096; i += NT) d0[i] = s0[i];
    }
    if (tid < H) { bk_s[tid] = bk[tid]; bv_s[tid] = bv[tid]; b1_s[tid] = b1[tid]; w2_s[tid] = W2[tid]; }
    __syncthreads();

    float inv_tc = 1.f / (fabsf(tcp[0]) + 1e-9f);
    float b2v = b2[0];

    // ---- per-warp GEMM tiling: m64 x n32, 2x8 warp grid ----
    int warp_row = wid & 1;
    int warp_col = wid >> 1;
    int n0 = warp_col * 32;
    bool isK = (n0 < 128);

    // ldmatrix A lane addressing
    int ra = lane & 7, ha = (lane >> 3) & 1, kh = lane >> 4;
    uint32_t aXor = (uint32_t)ra << 4;
    uint32_t aKh = (uint32_t)(kh * 16);
    uint32_t aRowBase = smb + OFF_A + (uint32_t)(warp_row * 64 + ha * 8 + ra) * 256u;

    // ldmatrix B lane addressing
    int qb = lane >> 3, rb = lane & 7;
    uint32_t bXor = (uint32_t)rb << 4;
    uint32_t bKh = (uint32_t)((qb & 1) * 16);
    uint32_t bRow0 = smb + OFF_B + (uint32_t)(n0 + (qb >> 1) * 8 + rb) * 256u;
    uint32_t bRow1 = bRow0 + 16u * 256u;

    int r4 = lane >> 2, c2 = (lane & 3) * 2;

    // gather mapping
    int ge = tid >> 2, gq = tid & 3;

    for (int t = blockIdx.x; t < ntiles; t += gridDim.x) {
        int e0 = t * TILE_E;
        int cnt = min(TILE_E, E - e0);

        // ---- phase 0: edge meta + time gate ----
        if (tid < TILE_E) {
            float tm = 0.f;
            if (tid < cnt) {
                int ee = e0 + tid;
                int d = dst[ee];
                src_s[tid] = src[ee]; dst_s[tid] = d; et_s[tid] = et[ee];
                float dt = (ts[d] - etime[ee]) * inv_tc;
                tm = 1.f / (1.f + expf(-dt));
            } else { src_s[tid] = 0; dst_s[tid] = 0; et_s[tid] = 0; }
            tm_s[tid] = tm;
        }
        __syncthreads();

        // ---- phase 1: gather g = x[src]*rel[et] -> fp16 A tile + dw ----
        {
            int sn = src_s[ge], rr = et_s[ge];
            float tme = tm_s[ge];
            const float4* xp  = (const float4*)(x     + (size_t)sn * H) + gq * 8;
            const float4* rp  = (const float4*)(rel   + (size_t)rr * H) + gq * 8;
            const float4* sp  = (const float4*)(g_S1  + (size_t)sn * H) + gq * 8;
            const float4* r2p = (const float4*)(g_R2x + (size_t)rr * H) + gq * 8;
            char* Ah = smc + OFF_A + ge * 256;
            unsigned xr = (unsigned)(ge & 7) << 4;
            float hacc = 0.f;
#pragma unroll
            for (int i = 0; i < 8; i++) {
                float4 xv = __ldg(xp + i), rv = __ldg(rp + i);
                float4 s1 = __ldg(sp + i), r2 = __ldg(r2p + i);
                int col = gq * 32 + i * 4;
                float4 b14 = *(const float4*)(b1_s + col);
                float4 w24 = *(const float4*)(w2_s + col);
                float g0 = xv.x * rv.x, g1 = xv.y * rv.y, g2 = xv.z * rv.z, g3 = xv.w * rv.w;
                hacc += fmaxf(fmaf(tme, r2.x, s1.x + b14.x), 0.f) * w24.x;
                hacc += fmaxf(fmaf(tme, r2.y, s1.y + b14.y), 0.f) * w24.y;
                hacc += fmaxf(fmaf(tme, r2.z, s1.z + b14.z), 0.f) * w24.z;
                hacc += fmaxf(fmaf(tme, r2.w, s1.w + b14.w), 0.f) * w24.w;
                __half2 h01 = __floats2half2_rn(g0, g1);
                __half2 h23 = __floats2half2_rn(g2, g3);
                unsigned kb = (unsigned)(gq * 64 + i * 8);
                uint2 uh; uh.x = *(unsigned*)&h01; uh.y = *(unsigned*)&h23;
                *(uint2*)(Ah + (kb ^ xr)) = uh;
            }
            // dw = sigmoid(h.W2+b2) reduced across the 4 lanes of this edge
            hacc += __shfl_xor_sync(0xFFFFFFFFu, hacc, 1);
            hacc += __shfl_xor_sync(0xFFFFFFFFu, hacc, 2);
            if ((tid & 3) == 0) {
                float dw = 1.f / (1.f + expf(-(hacc + b2v)));
                ss_s[ge] = tm_s[ge] * dw;
            }
        }
        __syncthreads();

        // ---- phase 2: GEMM 128x256x128 fp16 single pass, m64n32 per warp ----
        float acc[4][4][4];
#pragma unroll
        for (int mt = 0; mt < 4; mt++)
#pragma unroll
            for (int ng = 0; ng < 4; ng++)
#pragma unroll
                for (int i = 0; i < 4; i++) acc[mt][ng][i] = 0.f;

        for (int ks = 0; ks < 8; ks++) {
            uint32_t kbB = ((uint32_t)(ks * 32) + bKh) ^ bXor;
            uint32_t bh[8];
            ldsm4(bh + 0, bRow0 + kbB);
            ldsm4(bh + 4, bRow1 + kbB);
            uint32_t kbA = ((uint32_t)(ks * 32) + aKh) ^ aXor;
#pragma unroll
            for (int mt = 0; mt < 4; mt++) {
                uint32_t ah[4];
                ldsm4(ah, aRowBase + (uint32_t)(mt * 16) * 256u + kbA);
#pragma unroll
                for (int ng = 0; ng < 4; ng++)
                    mma16816(acc[mt][ng], ah, bh + ng * 2);
            }
        }
        __syncthreads();   // A tile no longer needed; KV buf aliases it

        // ---- stage K accums to smem (swizzled rows of 512B) ----
        if (isK) {
#pragma unroll
            for (int mt = 0; mt < 4; mt++) {
#pragma unroll
                for (int ng = 0; ng < 4; ng++) {
                    int ee = warp_row * 64 + mt * 16 + r4;
                    unsigned jb = (unsigned)((n0 + ng * 8 + c2) * 4);
                    char* base = smc + OFF_KV;
                    *(float2*)(base + ee * 512 + (jb ^ ((unsigned)(ee & 31) << 4))) =
                        make_float2(acc[mt][ng][0], acc[mt][ng][1]);
                    int ee2 = ee + 8;
                    *(float2*)(base + ee2 * 512 + (jb ^ ((unsigned)(ee2 & 31) << 4))) =
                        make_float2(acc[mt][ng][2], acc[mt][ng][3]);
                }
            }
        }
        __syncthreads();

        // ---- score phase: thread covers 32 cols (2 heads) of one edge ----
        {
            int qq = wid & 3;
            int e = (wid >> 2) * 32 + lane;
            int d2 = dst_s[e];
            float sce = ss_s[e];
            bool valid = (e < cnt);
            const float* qrow = g_Q + (size_t)d2 * H;
            char* kbase = smc + OFF_KV + e * 512;
            unsigned xr = (unsigned)(e & 31) << 4;
            float s0 = 0.f, s1 = 0.f;
#pragma unroll
            for (int i = 0; i < 8; i++) {
                unsigned jb = (unsigned)(qq * 128 + i * 16);
                float4 kr = *(float4*)(kbase + (jb ^ xr));
                int j = qq * 32 + i * 4;
                float4 q4 = __ldg((const float4*)(qrow + j));
                float k0 = fmaf(kr.x, sce, bk_s[j + 0]);
                float k1 = fmaf(kr.y, sce, bk_s[j + 1]);
                float k2 = fmaf(kr.z, sce, bk_s[j + 2]);
                float k3 = fmaf(kr.w, sce, bk_s[j + 3]);
                float dp = q4.x * k0 + q4.y * k1 + q4.z * k2 + q4.w * k3;
                if (i < 4) s0 += dp; else s1 += dp;
            }
            float w0 = expf(s0 * 0.25f);
            float w1 = expf(s1 * 0.25f);
            w_sm[e * 8 + 2 * qq + 0] = w0;
            w_sm[e * 8 + 2 * qq + 1] = w1;
            if (valid) {
                float* dp = &g_denom[(size_t)d2 * NHEAD + 2 * qq];
                asm volatile("red.global.add.v2.f32 [%0], {%1,%2};"
                             :: "l"(dp), "f"(w0), "f"(w1) : "memory");
            }
        }
        __syncthreads();

        // ---- stage V accums to smem (same buffer) ----
        if (!isK) {
#pragma unroll
            for (int mt = 0; mt < 4; mt++) {
#pragma unroll
                for (int ng = 0; ng < 4; ng++) {
                    int ee = warp_row * 64 + mt * 16 + r4;
                    unsigned jb = (unsigned)((n0 - 128 + ng * 8 + c2) * 4);
                    char* base = smc + OFF_KV;
                    *(float2*)(base + ee * 512 + (jb ^ ((unsigned)(ee & 31) << 4))) =
                        make_float2(acc[mt][ng][0], acc[mt][ng][1]);
                    int ee2 = ee + 8;
                    *(float2*)(base + ee2 * 512 + (jb ^ ((unsigned)(ee2 & 31) << 4))) =
                        make_float2(acc[mt][ng][2], acc[mt][ng][3]);
                }
            }
        }
        __syncthreads();

        // ---- V scatter phase ----
        {
            int qq = wid & 3;
            int e = (wid >> 2) * 32 + lane;
            int d2 = dst_s[e];
            float sce = ss_s[e];
            bool valid = (e < cnt);
            char* vbase = smc + OFF_KV + e * 512;
            unsigned xr = (unsigned)(e & 31) << 4;
            float* orow = out + (size_t)d2 * H;
#pragma unroll
            for (int i = 0; i < 8; i++) {
                unsigned jb = (unsigned)(qq * 128 + i * 16);
                float4 vr = *(float4*)(vbase + (jb ^ xr));
                int j = qq * 32 + i * 4;
                float ww = w_sm[e * 8 + 2 * qq + (i >> 2)];
                float v0 = fmaf(vr.x, sce, bv_s[j + 0]) * ww;
                float v1 = fmaf(vr.y, sce, bv_s[j + 1]) * ww;
                float v2 = fmaf(vr.z, sce, bv_s[j + 2]) * ww;
                float v3 = fmaf(vr.w, sce, bv_s[j + 3]) * ww;
                if (valid)
                    asm volatile("red.global.add.v4.f32 [%0], {%1,%2,%3,%4};"
                                 :: "l"(orow + j), "f"(v0), "f"(v1), "f"(v2), "f"(v3) : "memory");
            }
        }
        __syncthreads();
    }
}

// ---------------- normalize ------------------------------------------------
__global__ void k_norm(float* __restrict__ out, int N)
{
    int idx = blockIdx.x * blockDim.x + threadIdx.x;
    if (idx >= N * H) return;
    int n = idx >> 7, jj = idx & (H - 1);
    float dnm = g_denom[n * NHEAD + (jj >> 4)];
    float v = out[idx];
    out[idx] = (dnm > 0.f) ? v / dnm : 0.f;
}

// ---------------- launch ---------------------------------------------------
extern "C" void kernel_launch(void* const* d_in, const int* in_sizes, int n_in,
                              void* d_out, int out_size)
{
    const float* x     = (const float*)d_in[0];
    const float* ts    = (const float*)d_in[1];
    const int*   src   = (const int*)  d_in[2];
    const int*   dst   = (const int*)  d_in[3];
    const int*   etyp  = (const int*)  d_in[4];
    const float* etime = (const float*)d_in[5];
    const float* rel   = (const float*)d_in[6];
    const float* Wq    = (const float*)d_in[7];
    const float* bq    = (const float*)d_in[8];
    const float* Wk    = (const float*)d_in[9];
    const float* bk    = (const float*)d_in[10];
    const float* Wv    = (const float*)d_in[11];
    const float* bv    = (const float*)d_in[12];
    const float* W1    = (const float*)d_in[13];
    const float* b1    = (const float*)d_in[14];
    const float* W2    = (const float*)d_in[15];
    const float* b2    = (const float*)d_in[16];
    const float* tcp   = (const float*)d_in[17];

    int N    = in_sizes[0] / H;
    int E    = in_sizes[2];
    int NREL = in_sizes[6] / H;
    float* out = (float*)d_out;
    int ntiles = (E + TILE_E - 1) / TILE_E;

    static int smem_set = 0;
    if (!smem_set) {
        cudaFuncSetAttribute(k_edge_mma, cudaFuncAttributeMaxDynamicSharedMemorySize, SMEM_EDGE);
        smem_set = 1;
    }

    k_init <<<2048, 256>>>(out, N, out_size);
    k_rel  <<<NREL, H>>>(rel, W1);
    k_prepw<<<256, H>>>(Wk, Wv);
    k_node <<<(N + TEN - 1) / TEN, H>>>(x, Wq, bq, W1, N);
    k_edge_mma<<<148, NT, SMEM_EDGE>>>(x, ts, src, dst, etyp, etime, rel,
                                       bk, bv, b1, W2, b2, tcp, out, E, ntiles);
    k_norm <<<(N * H + 255) / 256, 256>>>(out, N);
}